// round 12
// baseline (speedup 1.0000x reference)
#include <cuda_runtime.h>
#include <cstdint>
#include <cfloat>

#define DL 21
#define SS 512
#define HW (SS*SS)
#define NB 4
#define NE (NB*DL*HW)   // 22,020,096 (~84 MB fp32)

// Spatially transposed unary (b,l,x,y) and edge weights for dirs 0/1
__device__ __align__(16) float g_uT[NE];
__device__ __align__(16) float g_ewT[NB*2*HW];
// Directional results: o0/o1 in transposed space; o2 carries -3u
__device__ __align__(16) float g_o0[NE];
__device__ __align__(16) float g_o1[NE];
__device__ __align__(16) float g_o2[NE];
__device__ __align__(16) float g_o3[NE];

// ---------------------------------------------------------------------------
// 32x32 tile transpose using float4, conflict-free padded tile
__device__ __forceinline__ void tr_tile4(const float* __restrict__ sp,
                                         float* __restrict__ dp, int tt, int tid) {
    __shared__ float tile[32][33];
    const int ty0 = (tt >> 4) << 5;
    const int tx0 = (tt & 15) << 5;
    const int r  = tid >> 3;
    const int q4 = (tid & 7) << 2;
    float4 v = *reinterpret_cast<const float4*>(sp + (size_t)(ty0 + r) * SS + tx0 + q4);
    tile[r][q4 + 0] = v.x; tile[r][q4 + 1] = v.y;
    tile[r][q4 + 2] = v.z; tile[r][q4 + 3] = v.w;
    __syncthreads();
    float4 o = make_float4(tile[q4 + 0][r], tile[q4 + 1][r],
                           tile[q4 + 2][r], tile[q4 + 3][r]);
    *reinterpret_cast<float4*>(dp + (size_t)(tx0 + r) * SS + ty0 + q4) = o;
}

// planes 0..83: unary; 84..91: edge weights dirs 0/1
__global__ void __launch_bounds__(256)
transpose_all(const float* __restrict__ u, const float* __restrict__ ew) {
    const int plane = blockIdx.x >> 8;
    const int tt = blockIdx.x & 255;
    if (plane < NB * DL) {
        tr_tile4(u + (size_t)plane * HW, g_uT + (size_t)plane * HW, tt, threadIdx.x);
    } else {
        const int p = plane - NB * DL;          // 0..7
        const int b = p >> 1, d = p & 1;
        tr_tile4(ew + (size_t)(b * 4 + d) * HW, g_ewT + (size_t)p * HW, tt, threadIdx.x);
    }
}

// ---------------------------------------------------------------------------
// Sweep: warp-private chains. Each warp owns 4 columns; lane (c = lane&3,
// g = lane>>2) holds labels 3g..3g+2 of column c (g<7 active). Per step the
// 21 L values of a column are exchanged with 21 warp-wide shuffles serving
// all 4 columns at once. NO barriers, NO shared memory -> warps are fully
// independent and pipe phases overlap across the 13.8 warps/SM.
template<int DIR>
__device__ __forceinline__ void run_sweep(const float* __restrict__ u,
                                          const float* __restrict__ ew,
                                          int b, int base0, int wb, int c,
                                          bool active,
                                          const float (&V0)[DL],
                                          const float (&V1)[DL],
                                          const float (&V2)[DL]) {
    const float* src  = (DIR < 2) ? g_uT : u;
    const float* wsrc = (DIR < 2) ? (g_ewT + (size_t)(b * 2 + DIR) * HW)
                                  : (ew   + (size_t)(b * 4 + DIR) * HW);
    float* dst = (DIR == 0) ? g_o0 : (DIR == 1) ? g_o1 : (DIR == 2) ? g_o2 : g_o3;
    constexpr int STRD = (DIR == 0 || DIR == 2) ? SS : -SS;
    const int start = (STRD > 0) ? 0 : (SS - 1) * SS;
    const int base1 = base0 + HW;
    const int base2 = base0 + 2 * HW;
    const unsigned FM = 0xffffffffu;

    float L0, L1, L2;
    // t = 0 (border: L = u)
    {
        float cu0 = __ldg(src + base0 + start);
        float cu1 = __ldg(src + base1 + start);
        float cu2 = __ldg(src + base2 + start);
        L0 = cu0; L1 = cu1; L2 = cu2;
        if (active) {
            dst[base0 + start] = (DIR == 2) ? fmaf(-3.0f, cu0, L0) : L0;
            dst[base1 + start] = (DIR == 2) ? fmaf(-3.0f, cu1, L1) : L1;
            dst[base2 + start] = (DIR == 2) ? fmaf(-3.0f, cu2, L2) : L2;
        }
    }
    // depth-2 prefetch
    int offL = start + STRD;
    float au0 = __ldg(src + base0 + offL);
    float au1 = __ldg(src + base1 + offL);
    float au2 = __ldg(src + base2 + offL);
    float aw  = __ldg(wsrc + wb + offL);
    offL += STRD;
    float bu0 = __ldg(src + base0 + offL);
    float bu1 = __ldg(src + base1 + offL);
    float bu2 = __ldg(src + base2 + offL);
    float bw  = __ldg(wsrc + wb + offL);

    auto stepf = [&](float u0v, float u1v, float u2v, float wv, int offS) {
        // 3 accumulator chains per label; s_k = L[k] of this column via shfl
        float m00, m01, m02, m10, m11, m12, m20, m21, m22;
#pragma unroll
        for (int k = 0; k < DL; k++) {
            const float lsrc = (k % 3 == 0) ? L0 : (k % 3 == 1) ? L1 : L2;
            const float sk = __shfl_sync(FM, lsrc, (k / 3) * 4 + c);
            if (k == 0)      { m00 = fmaf(wv, V0[0], sk); m10 = fmaf(wv, V1[0], sk); m20 = fmaf(wv, V2[0], sk); }
            else if (k == 1) { m01 = fmaf(wv, V0[1], sk); m11 = fmaf(wv, V1[1], sk); m21 = fmaf(wv, V2[1], sk); }
            else if (k == 2) { m02 = fmaf(wv, V0[2], sk); m12 = fmaf(wv, V1[2], sk); m22 = fmaf(wv, V2[2], sk); }
            else {
                const int r3 = k % 3;
                if (r3 == 0) { m00 = fminf(m00, fmaf(wv, V0[k], sk)); m10 = fminf(m10, fmaf(wv, V1[k], sk)); m20 = fminf(m20, fmaf(wv, V2[k], sk)); }
                else if (r3 == 1) { m01 = fminf(m01, fmaf(wv, V0[k], sk)); m11 = fminf(m11, fmaf(wv, V1[k], sk)); m21 = fminf(m21, fmaf(wv, V2[k], sk)); }
                else { m02 = fminf(m02, fmaf(wv, V0[k], sk)); m12 = fminf(m12, fmaf(wv, V1[k], sk)); m22 = fminf(m22, fmaf(wv, V2[k], sk)); }
            }
        }
        L0 = u0v + fminf(m00, fminf(m01, m02));
        L1 = u1v + fminf(m10, fminf(m11, m12));
        L2 = u2v + fminf(m20, fminf(m21, m22));
        if (active) {
            dst[base0 + offS] = (DIR == 2) ? fmaf(-3.0f, u0v, L0) : L0;
            dst[base1 + offS] = (DIR == 2) ? fmaf(-3.0f, u1v, L1) : L1;
            dst[base2 + offS] = (DIR == 2) ? fmaf(-3.0f, u2v, L2) : L2;
        }
    };

    int offS = start;
#pragma unroll 1
    for (int t = 1; t <= SS - 3; t++) {
        offS += STRD;
        offL += STRD;
        // next loads issued first so they fly during compute
        float nu0 = __ldg(src + base0 + offL);
        float nu1 = __ldg(src + base1 + offL);
        float nu2 = __ldg(src + base2 + offL);
        float nw  = __ldg(wsrc + wb + offL);
        stepf(au0, au1, au2, aw, offS);
        au0 = bu0; au1 = bu1; au2 = bu2; aw = bw;
        bu0 = nu0; bu1 = nu1; bu2 = nu2; bw = nw;
    }
    // t = SS-2
    offS += STRD;
    stepf(au0, au1, au2, aw, offS);
    // t = SS-1
    offS += STRD;
    stepf(bu0, bu1, bu2, bw, offS);
}

__global__ void __launch_bounds__(256, 2)
sweep(const float* __restrict__ u, const float* __restrict__ ew,
      const float* __restrict__ lc) {
    const int bx   = blockIdx.x;              // 256 blocks x 8 warps
    const int dir  = bx >> 6;
    const int b    = (bx >> 4) & 3;
    const int col0 = (bx & 15) << 5;
    const int wid  = threadIdx.x >> 5;
    const int lane = threadIdx.x & 31;
    const int c    = lane & 3;
    const int g    = lane >> 2;               // 0..7
    const bool active = (g < 7);
    const int gg   = active ? g : 6;
    const int l0   = 3 * gg;
    const int col  = col0 + (wid << 2) + c;

    // V columns for this lane's 3 labels: Vj[k] = V[k][l0+j]
    float V0[DL], V1[DL], V2[DL];
#pragma unroll
    for (int k = 0; k < DL; k++) {
        V0[k] = __ldg(lc + k * DL + l0);
        V1[k] = __ldg(lc + k * DL + l0 + 1);
        V2[k] = __ldg(lc + k * DL + l0 + 2);
    }

    const int base0 = (b * DL + l0) * HW + col;

    if (dir == 0)      run_sweep<0>(u, ew, b, base0, col, c, active, V0, V1, V2);
    else if (dir == 1) run_sweep<1>(u, ew, b, base0, col, c, active, V0, V1, V2);
    else if (dir == 2) run_sweep<2>(u, ew, b, base0, col, c, active, V0, V1, V2);
    else               run_sweep<3>(u, ew, b, base0, col, c, active, V0, V1, V2);
}

// ---------------------------------------------------------------------------
// out(b,l,y,x) = o2(y,x) + o3(y,x) + o0(x,y) + o1(x,y)   [o2 carries -3u]
__global__ void __launch_bounds__(256)
combine(float* __restrict__ out) {
    __shared__ float t0[32][33], t1[32][33];
    const int plane = blockIdx.x >> 8;       // b*21+l
    const int tt = blockIdx.x & 255;
    const int y0 = (tt >> 4) << 5;
    const int x0 = (tt & 15) << 5;
    const size_t pb = (size_t)plane * HW;
    const int r  = threadIdx.x >> 3;
    const int q4 = (threadIdx.x & 7) << 2;
    {   // load transposed planes: rows along x, vectorized along y
        size_t idx = pb + (size_t)(x0 + r) * SS + y0 + q4;
        float4 a = *reinterpret_cast<const float4*>(g_o0 + idx);
        float4 bq = *reinterpret_cast<const float4*>(g_o1 + idx);
        t0[r][q4 + 0] = a.x;  t0[r][q4 + 1] = a.y;
        t0[r][q4 + 2] = a.z;  t0[r][q4 + 3] = a.w;
        t1[r][q4 + 0] = bq.x; t1[r][q4 + 1] = bq.y;
        t1[r][q4 + 2] = bq.z; t1[r][q4 + 3] = bq.w;
    }
    __syncthreads();
    {   // stream o2/o3 + add transposed tiles, vectorized along x
        size_t idx = pb + (size_t)(y0 + r) * SS + x0 + q4;
        float4 r2 = *reinterpret_cast<const float4*>(g_o2 + idx);
        float4 r3 = *reinterpret_cast<const float4*>(g_o3 + idx);
        float4 o;
        o.x = r2.x + r3.x + t0[q4 + 0][r] + t1[q4 + 0][r];
        o.y = r2.y + r3.y + t0[q4 + 1][r] + t1[q4 + 1][r];
        o.z = r2.z + r3.z + t0[q4 + 2][r] + t1[q4 + 2][r];
        o.w = r2.w + r3.w + t0[q4 + 3][r] + t1[q4 + 3][r];
        *reinterpret_cast<float4*>(out + idx) = o;
    }
}

// ---------------------------------------------------------------------------
extern "C" void kernel_launch(void* const* d_in, const int* in_sizes, int n_in,
                              void* d_out, int out_size) {
    const float* unary = (const float*)d_in[0];   // (4,1,21,512,512)
    const float* ew    = (const float*)d_in[1];   // (4,4,512,512)
    const float* lc    = (const float*)d_in[2];   // (21,21)
    float* out = (float*)d_out;                   // (4,1,21,512,512)

    transpose_all<<<(NB * DL + NB * 2) * 256, 256>>>(unary, ew);
    sweep<<<256, 256>>>(unary, ew, lc);
    combine<<<NB * DL * 256, 256>>>(out);
}

// round 13
// speedup vs baseline: 1.3828x; 1.3828x over previous
#include <cuda_runtime.h>
#include <cstdint>

#define DL 21
#define SS 512
#define HW (SS*SS)
#define NB 4
#define NE (NB*DL*HW)   // 22,020,096 (~84 MB fp32)

// (b,l) planes transposed spatially: [x][y]
__device__ __align__(16) float g_uT[NE];
__device__ __align__(16) float g_ewT[NB*2*HW];
// Label-innermost unary: (b, p'=x*512+y, l)   (+pad: lanes may read l0+2 dummy)
__device__ __align__(16) float g_ux[NE + 64];
// Directional results, label-innermost, p = y*512+x (y-major). o2 carries -3u.
__device__ __align__(16) float g_o0[NE + 64];
__device__ __align__(16) float g_o1[NE + 64];
__device__ __align__(16) float g_o2[NE + 64];
__device__ __align__(16) float g_o3[NE + 64];

// ---------------------------------------------------------------------------
// 32x32 tile transpose using float4, conflict-free padded tile
__device__ __forceinline__ void tr_tile4(const float* __restrict__ sp,
                                         float* __restrict__ dp, int tt, int tid) {
    __shared__ float tile[32][33];
    const int ty0 = (tt >> 4) << 5;
    const int tx0 = (tt & 15) << 5;
    const int r  = tid >> 3;
    const int q4 = (tid & 7) << 2;
    float4 v = *reinterpret_cast<const float4*>(sp + (size_t)(ty0 + r) * SS + tx0 + q4);
    tile[r][q4 + 0] = v.x; tile[r][q4 + 1] = v.y;
    tile[r][q4 + 2] = v.z; tile[r][q4 + 3] = v.w;
    __syncthreads();
    float4 o = make_float4(tile[q4 + 0][r], tile[q4 + 1][r],
                           tile[q4 + 2][r], tile[q4 + 3][r]);
    *reinterpret_cast<float4*>(dp + (size_t)(tx0 + r) * SS + ty0 + q4) = o;
}

// planes 0..83: unary -> g_uT; 84..91: edge weights dirs 0/1 -> g_ewT
__global__ void __launch_bounds__(256)
transpose_all(const float* __restrict__ u, const float* __restrict__ ew) {
    const int plane = blockIdx.x >> 8;
    const int tt = blockIdx.x & 255;
    if (plane < NB * DL) {
        tr_tile4(u + (size_t)plane * HW, g_uT + (size_t)plane * HW, tt, threadIdx.x);
    } else {
        const int p = plane - NB * DL;          // 0..7
        const int b = p >> 1, d = p & 1;
        tr_tile4(ew + (size_t)(b * 4 + d) * HW, g_ewT + (size_t)p * HW, tt, threadIdx.x);
    }
}

// ---------------------------------------------------------------------------
// Label transpose: g_ux[(b*HW + p)*21 + l] = g_uT[(b*21 + l)*HW + p]
__global__ void __launch_bounds__(256)
ltrans() {
    __shared__ float tile[DL][132];
    const int blk = blockIdx.x;               // 8192
    const int b  = blk >> 11;
    const int p0 = (blk & 2047) << 7;
    for (int j = threadIdx.x; j < DL * 32; j += 256) {
        const int l = j >> 5, i4 = (j & 31) << 2;
        float4 v = *reinterpret_cast<const float4*>(
            g_uT + (size_t)(b * DL + l) * HW + p0 + i4);
        tile[l][i4 + 0] = v.x; tile[l][i4 + 1] = v.y;
        tile[l][i4 + 2] = v.z; tile[l][i4 + 3] = v.w;
    }
    __syncthreads();
    float* ob = g_ux + ((size_t)b * HW + p0) * DL;
    for (int j = threadIdx.x; j < (DL * 128) / 4; j += 256) {
        const int f = j << 2;
        float4 o;
        o.x = tile[(f + 0) % DL][(f + 0) / DL];
        o.y = tile[(f + 1) % DL][(f + 1) / DL];
        o.z = tile[(f + 2) % DL][(f + 2) / DL];
        o.w = tile[(f + 3) % DL][(f + 3) / DL];
        *reinterpret_cast<float4*>(ob + f) = o;
    }
}

// ---------------------------------------------------------------------------
// Sweep: warp = 4 columns x 8 label-split threads. Thread (col, s) owns
// output labels: s<5 -> {3s,3s+1,3s+2}; s=5/6/7 -> {15,16}/{17,18}/{19,20}.
// Exchange = 21 shfl per step (all L values to all lanes). Zero barriers.
template<int DIR>
__device__ __forceinline__ void run_sweep(const float* __restrict__ ew,
                                          int b, int col, int l0, bool full3,
                                          int baseLane,
                                          const float (&V0)[DL],
                                          const float (&V1)[DL],
                                          const float (&V2)[DL]) {
    const unsigned FM = 0xffffffffu;
    const float* ux = g_ux + (size_t)b * HW * DL;
    float* dst = ((DIR == 0) ? g_o0 : (DIR == 1) ? g_o1 : (DIR == 2) ? g_o2 : g_o3)
                 + (size_t)b * HW * DL;
    const float* warr;
    int ridx, rstr, sidx, sstr, widx, wstr;
    if (DIR == 0) {        // L->R: chain y=col, t=x; read (x*512+col), store (col*512+x)
        ridx = col * DL + l0;                 rstr =  SS * DL;
        sidx = (col * SS) * DL + l0;          sstr =  DL;
        warr = g_ewT + (size_t)(b * 2 + 0) * HW; widx = col;              wstr =  SS;
    } else if (DIR == 1) { // R->L
        ridx = ((SS-1) * SS + col) * DL + l0; rstr = -SS * DL;
        sidx = (col * SS + SS - 1) * DL + l0; sstr = -DL;
        warr = g_ewT + (size_t)(b * 2 + 1) * HW; widx = (SS-1)*SS + col;  wstr = -SS;
    } else if (DIR == 2) { // T->D: chain x=col, t=y; read (col*512+y), store (y*512+col)
        ridx = (col * SS) * DL + l0;          rstr =  DL;
        sidx = col * DL + l0;                 sstr =  SS * DL;
        warr = ew + (size_t)(b * 4 + 2) * HW;    widx = col;              wstr =  SS;
    } else {               // B->U
        ridx = (col * SS + SS - 1) * DL + l0; rstr = -DL;
        sidx = ((SS-1) * SS + col) * DL + l0; sstr = -SS * DL;
        warr = ew + (size_t)(b * 4 + 3) * HW;    widx = (SS-1)*SS + col;  wstr = -SS;
    }

    float L0, L1, L2;
    {   // t = 0 border: L = u
        float u0 = __ldg(ux + ridx), u1 = __ldg(ux + ridx + 1), u2 = __ldg(ux + ridx + 2);
        L0 = u0; L1 = u1; L2 = u2;
        if (DIR == 2) {
            dst[sidx]     = fmaf(-3.0f, u0, L0);
            dst[sidx + 1] = fmaf(-3.0f, u1, L1);
            if (full3) dst[sidx + 2] = fmaf(-3.0f, u2, L2);
        } else {
            dst[sidx] = L0; dst[sidx + 1] = L1;
            if (full3) dst[sidx + 2] = L2;
        }
    }
    // depth-2 prefetch
    int rp = ridx + rstr, wp = widx + wstr;
    float au0 = __ldg(ux + rp), au1 = __ldg(ux + rp + 1), au2 = __ldg(ux + rp + 2);
    float aw  = __ldg(warr + wp);
    rp += rstr; wp += wstr;
    float bu0 = __ldg(ux + rp), bu1 = __ldg(ux + rp + 1), bu2 = __ldg(ux + rp + 2);
    float bw  = __ldg(warr + wp);

    auto step = [&](float u0, float u1, float u2, float w, int so) {
        const float P0 = L0, P1 = L1, P2 = L2;
        float m0a, m0b, m1a, m1b, m2a, m2b;
#pragma unroll
        for (int k = 0; k < DL; k++) {
            const int qk = (k < 15) ? k / 3 : 5 + (k - 15) / 2;
            const int sl = (k < 15) ? k % 3 : (k - 15) & 1;
            const float Lk = __shfl_sync(FM, sl == 0 ? P0 : (sl == 1 ? P1 : P2),
                                         baseLane | qk);
            const float c0 = fmaf(w, V0[k], Lk);
            const float c1 = fmaf(w, V1[k], Lk);
            const float c2 = fmaf(w, V2[k], Lk);
            if (k == 0)      { m0a = c0; m1a = c1; m2a = c2; }
            else if (k == 1) { m0b = c0; m1b = c1; m2b = c2; }
            else if ((k & 1) == 0) { m0a = fminf(m0a, c0); m1a = fminf(m1a, c1); m2a = fminf(m2a, c2); }
            else             { m0b = fminf(m0b, c0); m1b = fminf(m1b, c1); m2b = fminf(m2b, c2); }
        }
        L0 = u0 + fminf(m0a, m0b);
        L1 = u1 + fminf(m1a, m1b);
        L2 = u2 + fminf(m2a, m2b);
        if (DIR == 2) {
            dst[so]     = fmaf(-3.0f, u0, L0);
            dst[so + 1] = fmaf(-3.0f, u1, L1);
            if (full3) dst[so + 2] = fmaf(-3.0f, u2, L2);
        } else {
            dst[so] = L0; dst[so + 1] = L1;
            if (full3) dst[so + 2] = L2;
        }
    };

    int sp = sidx;
#pragma unroll 1
    for (int t = 1; t <= SS - 3; t++) {
        rp += rstr; wp += wstr;
        float nu0 = __ldg(ux + rp), nu1 = __ldg(ux + rp + 1), nu2 = __ldg(ux + rp + 2);
        float nw  = __ldg(warr + wp);
        sp += sstr;
        step(au0, au1, au2, aw, sp);
        au0 = bu0; au1 = bu1; au2 = bu2; aw = bw;
        bu0 = nu0; bu1 = nu1; bu2 = nu2; bw = nw;
    }
    sp += sstr; step(au0, au1, au2, aw, sp);
    sp += sstr; step(bu0, bu1, bu2, bw, sp);
}

__global__ void __launch_bounds__(64, 8)
sweep(const float* __restrict__ ew, const float* __restrict__ lc) {
    const int bx   = blockIdx.x;              // 1024 blocks x 2 warps
    const int dir  = bx >> 8;
    const int b    = (bx >> 6) & 3;
    const int cg   = bx & 63;
    const int lane = threadIdx.x & 31;
    const int s    = lane & 7;
    const int col  = (cg << 3) + ((threadIdx.x >> 5) << 2) + (lane >> 3);
    const bool full3 = (s < 5);
    const int l0 = full3 ? 3 * s : 15 + 2 * (s - 5);
    const int l1 = l0 + 1;
    const int l2 = full3 ? l0 + 2 : l1;      // dup for 2-label lanes (never sourced)
    const int baseLane = lane & 24;

    float V0[DL], V1[DL], V2[DL];
#pragma unroll
    for (int k = 0; k < DL; k++) {
        V0[k] = __ldg(lc + k * DL + l0);
        V1[k] = __ldg(lc + k * DL + l1);
        V2[k] = __ldg(lc + k * DL + l2);
    }

    if (dir == 0)      run_sweep<0>(ew, b, col, l0, full3, baseLane, V0, V1, V2);
    else if (dir == 1) run_sweep<1>(ew, b, col, l0, full3, baseLane, V0, V1, V2);
    else if (dir == 2) run_sweep<2>(ew, b, col, l0, full3, baseLane, V0, V1, V2);
    else               run_sweep<3>(ew, b, col, l0, full3, baseLane, V0, V1, V2);
}

// ---------------------------------------------------------------------------
// out[(b*21+l)*HW + p] = (o0+o1+o2+o3)[(b*HW+p)*21 + l]   (o2 carries -3u)
__global__ void __launch_bounds__(256)
combine(float* __restrict__ out) {
    __shared__ float tile[DL][132];
    const int blk = blockIdx.x;               // 8192
    const int b  = blk >> 11;
    const int p0 = (blk & 2047) << 7;
    const size_t ib = ((size_t)b * HW + p0) * DL;
    for (int j = threadIdx.x; j < (DL * 128) / 4; j += 256) {
        const int f = j << 2;
        float4 a  = *reinterpret_cast<const float4*>(g_o0 + ib + f);
        float4 b4 = *reinterpret_cast<const float4*>(g_o1 + ib + f);
        float4 c  = *reinterpret_cast<const float4*>(g_o2 + ib + f);
        float4 d  = *reinterpret_cast<const float4*>(g_o3 + ib + f);
        tile[(f + 0) % DL][(f + 0) / DL] = a.x + b4.x + c.x + d.x;
        tile[(f + 1) % DL][(f + 1) / DL] = a.y + b4.y + c.y + d.y;
        tile[(f + 2) % DL][(f + 2) / DL] = a.z + b4.z + c.z + d.z;
        tile[(f + 3) % DL][(f + 3) / DL] = a.w + b4.w + c.w + d.w;
    }
    __syncthreads();
    for (int j = threadIdx.x; j < DL * 32; j += 256) {
        const int l = j >> 5, i4 = (j & 31) << 2;
        float4 o = make_float4(tile[l][i4], tile[l][i4 + 1],
                               tile[l][i4 + 2], tile[l][i4 + 3]);
        *reinterpret_cast<float4*>(out + (size_t)(b * DL + l) * HW + p0 + i4) = o;
    }
}

// ---------------------------------------------------------------------------
extern "C" void kernel_launch(void* const* d_in, const int* in_sizes, int n_in,
                              void* d_out, int out_size) {
    const float* unary = (const float*)d_in[0];   // (4,1,21,512,512)
    const float* ew    = (const float*)d_in[1];   // (4,4,512,512)
    const float* lc    = (const float*)d_in[2];   // (21,21)
    float* out = (float*)d_out;                   // (4,1,21,512,512)

    transpose_all<<<(NB * DL + NB * 2) * 256, 256>>>(unary, ew);
    ltrans<<<8192, 256>>>();
    sweep<<<1024, 64>>>(ew, lc);
    combine<<<8192, 256>>>(out);
}

// round 14
// speedup vs baseline: 1.4234x; 1.0294x over previous
#include <cuda_runtime.h>
#include <cstdint>

#define DL 21
#define SS 512
#define HW (SS*SS)
#define NB 4
#define NE (NB*DL*HW)   // 22,020,096 (~84 MB fp32)

// ew planes for dirs 0/1, spatially transposed: [x][y]
__device__ __align__(16) float g_ewT[NB*2*HW];
// Label-innermost unary: (b, p'=x*512+y, l)   (+pad: lanes may read l0+2 dummy)
__device__ __align__(16) float g_ux[NE + 64];
// Directional results, label-innermost, p = y*512+x (y-major). o2 carries -3u.
__device__ __align__(16) float g_o0[NE + 64];
__device__ __align__(16) float g_o1[NE + 64];
__device__ __align__(16) float g_o2[NE + 64];
__device__ __align__(16) float g_o3[NE + 64];

// ---------------------------------------------------------------------------
// Fused transpose: g_ux[(b, x*512+y, l)] = u[b, l, y, x]
// Block: one 32x32 spatial tile of one batch, all 21 labels, in 4 sub-chunks
// of 8 y-rows. smem layout [yy][l][x] with 33-float l-stride: both phases
// conflict-free (write phase: consecutive output elems map to distinct banks).
__global__ void __launch_bounds__(256)
ufuse(const float* __restrict__ u) {
    __shared__ float tile[8 * 693];           // yy*693 + l*33 + x  (22.2 KB)
    const int blk = blockIdx.x;               // 1024 = 4 b x 256 tiles
    const int b  = blk >> 8;
    const int t  = blk & 255;
    const int y0 = (t >> 4) << 5;
    const int x0 = (t & 15) << 5;

    for (int sc = 0; sc < 4; sc++) {
        if (sc) __syncthreads();
        // load: 21 l x 8 yy x 32 x, coalesced 128B rows
        for (int j = threadIdx.x; j < DL * 8 * 32; j += 256) {
            const int l  = j >> 8;
            const int yy = (j >> 5) & 7;
            const int xx = j & 31;
            tile[yy * 693 + l * 33 + xx] =
                u[((size_t)(b * DL + l) * SS + (y0 + (sc << 3) + yy)) * SS + x0 + xx];
        }
        __syncthreads();
        // store: for each x, 8*21 = 168 contiguous floats
        for (int j = threadIdx.x; j < 32 * 168; j += 256) {
            const int x = j / 168;
            const int r = j - x * 168;
            const int yy = r / DL;
            const int l  = r - yy * DL;
            g_ux[((size_t)b * HW + (size_t)(x0 + x) * SS + y0 + (sc << 3)) * DL + r]
                = tile[yy * 693 + l * 33 + x];
        }
    }
}

// ---------------------------------------------------------------------------
// 32x32 tile transpose (ew planes for dirs 0/1 only)
__global__ void __launch_bounds__(256)
transpose_ew(const float* __restrict__ ew) {
    __shared__ float tile[32][33];
    const int p  = blockIdx.x >> 8;           // 0..7 : b*2+d
    const int tt = blockIdx.x & 255;
    const int b = p >> 1, d = p & 1;
    const float* sp = ew + (size_t)(b * 4 + d) * HW;
    float* dp = g_ewT + (size_t)p * HW;
    const int ty0 = (tt >> 4) << 5;
    const int tx0 = (tt & 15) << 5;
    const int r  = threadIdx.x >> 3;
    const int q4 = (threadIdx.x & 7) << 2;
    float4 v = *reinterpret_cast<const float4*>(sp + (size_t)(ty0 + r) * SS + tx0 + q4);
    tile[r][q4 + 0] = v.x; tile[r][q4 + 1] = v.y;
    tile[r][q4 + 2] = v.z; tile[r][q4 + 3] = v.w;
    __syncthreads();
    float4 o = make_float4(tile[q4 + 0][r], tile[q4 + 1][r],
                           tile[q4 + 2][r], tile[q4 + 3][r]);
    *reinterpret_cast<float4*>(dp + (size_t)(tx0 + r) * SS + ty0 + q4) = o;
}

// ---------------------------------------------------------------------------
// Sweep: warp = 4 columns x 8 label-split threads. Thread (col, s) owns
// output labels: s<5 -> {3s,3s+1,3s+2}; s=5/6/7 -> {15,16}/{17,18}/{19,20}.
// Exchange = 21 shfl per step (all L values to all lanes). Zero barriers.
template<int DIR>
__device__ __forceinline__ void run_sweep(const float* __restrict__ ew,
                                          int b, int col, int l0, bool full3,
                                          int baseLane,
                                          const float (&V0)[DL],
                                          const float (&V1)[DL],
                                          const float (&V2)[DL]) {
    const unsigned FM = 0xffffffffu;
    const float* ux = g_ux + (size_t)b * HW * DL;
    float* dst = ((DIR == 0) ? g_o0 : (DIR == 1) ? g_o1 : (DIR == 2) ? g_o2 : g_o3)
                 + (size_t)b * HW * DL;
    const float* warr;
    int ridx, rstr, sidx, sstr, widx, wstr;
    if (DIR == 0) {        // L->R: chain y=col, t=x; read (x*512+col), store (col*512+x)
        ridx = col * DL + l0;                 rstr =  SS * DL;
        sidx = (col * SS) * DL + l0;          sstr =  DL;
        warr = g_ewT + (size_t)(b * 2 + 0) * HW; widx = col;              wstr =  SS;
    } else if (DIR == 1) { // R->L
        ridx = ((SS-1) * SS + col) * DL + l0; rstr = -SS * DL;
        sidx = (col * SS + SS - 1) * DL + l0; sstr = -DL;
        warr = g_ewT + (size_t)(b * 2 + 1) * HW; widx = (SS-1)*SS + col;  wstr = -SS;
    } else if (DIR == 2) { // T->D: chain x=col, t=y; read (col*512+y), store (y*512+col)
        ridx = (col * SS) * DL + l0;          rstr =  DL;
        sidx = col * DL + l0;                 sstr =  SS * DL;
        warr = ew + (size_t)(b * 4 + 2) * HW;    widx = col;              wstr =  SS;
    } else {               // B->U
        ridx = (col * SS + SS - 1) * DL + l0; rstr = -DL;
        sidx = ((SS-1) * SS + col) * DL + l0; sstr = -SS * DL;
        warr = ew + (size_t)(b * 4 + 3) * HW;    widx = (SS-1)*SS + col;  wstr = -SS;
    }

    float L0, L1, L2;
    {   // t = 0 border: L = u
        float u0 = __ldg(ux + ridx), u1 = __ldg(ux + ridx + 1), u2 = __ldg(ux + ridx + 2);
        L0 = u0; L1 = u1; L2 = u2;
        if (DIR == 2) {
            dst[sidx]     = fmaf(-3.0f, u0, L0);
            dst[sidx + 1] = fmaf(-3.0f, u1, L1);
            if (full3) dst[sidx + 2] = fmaf(-3.0f, u2, L2);
        } else {
            dst[sidx] = L0; dst[sidx + 1] = L1;
            if (full3) dst[sidx + 2] = L2;
        }
    }
    // depth-2 prefetch
    int rp = ridx + rstr, wp = widx + wstr;
    float au0 = __ldg(ux + rp), au1 = __ldg(ux + rp + 1), au2 = __ldg(ux + rp + 2);
    float aw  = __ldg(warr + wp);
    rp += rstr; wp += wstr;
    float bu0 = __ldg(ux + rp), bu1 = __ldg(ux + rp + 1), bu2 = __ldg(ux + rp + 2);
    float bw  = __ldg(warr + wp);

    auto step = [&](float u0, float u1, float u2, float w, int so) {
        const float P0 = L0, P1 = L1, P2 = L2;
        float m0a, m0b, m1a, m1b, m2a, m2b;
#pragma unroll
        for (int k = 0; k < DL; k++) {
            const int qk = (k < 15) ? k / 3 : 5 + (k - 15) / 2;
            const int sl = (k < 15) ? k % 3 : (k - 15) & 1;
            const float Lk = __shfl_sync(FM, sl == 0 ? P0 : (sl == 1 ? P1 : P2),
                                         baseLane | qk);
            const float c0 = fmaf(w, V0[k], Lk);
            const float c1 = fmaf(w, V1[k], Lk);
            const float c2 = fmaf(w, V2[k], Lk);
            if (k == 0)      { m0a = c0; m1a = c1; m2a = c2; }
            else if (k == 1) { m0b = c0; m1b = c1; m2b = c2; }
            else if ((k & 1) == 0) { m0a = fminf(m0a, c0); m1a = fminf(m1a, c1); m2a = fminf(m2a, c2); }
            else             { m0b = fminf(m0b, c0); m1b = fminf(m1b, c1); m2b = fminf(m2b, c2); }
        }
        L0 = u0 + fminf(m0a, m0b);
        L1 = u1 + fminf(m1a, m1b);
        L2 = u2 + fminf(m2a, m2b);
        if (DIR == 2) {
            dst[so]     = fmaf(-3.0f, u0, L0);
            dst[so + 1] = fmaf(-3.0f, u1, L1);
            if (full3) dst[so + 2] = fmaf(-3.0f, u2, L2);
        } else {
            dst[so] = L0; dst[so + 1] = L1;
            if (full3) dst[so + 2] = L2;
        }
    };

    int sp = sidx;
#pragma unroll 1
    for (int t = 1; t <= SS - 3; t++) {
        rp += rstr; wp += wstr;
        float nu0 = __ldg(ux + rp), nu1 = __ldg(ux + rp + 1), nu2 = __ldg(ux + rp + 2);
        float nw  = __ldg(warr + wp);
        sp += sstr;
        step(au0, au1, au2, aw, sp);
        au0 = bu0; au1 = bu1; au2 = bu2; aw = bw;
        bu0 = nu0; bu1 = nu1; bu2 = nu2; bw = nw;
    }
    sp += sstr; step(au0, au1, au2, aw, sp);
    sp += sstr; step(bu0, bu1, bu2, bw, sp);
}

__global__ void __launch_bounds__(64, 8)
sweep(const float* __restrict__ ew, const float* __restrict__ lc) {
    const int bx   = blockIdx.x;              // 1024 blocks x 2 warps
    const int dir  = bx >> 8;
    const int b    = (bx >> 6) & 3;
    const int cg   = bx & 63;
    const int lane = threadIdx.x & 31;
    const int s    = lane & 7;
    const int col  = (cg << 3) + ((threadIdx.x >> 5) << 2) + (lane >> 3);
    const bool full3 = (s < 5);
    const int l0 = full3 ? 3 * s : 15 + 2 * (s - 5);
    const int l1 = l0 + 1;
    const int l2 = full3 ? l0 + 2 : l1;      // dup for 2-label lanes (never sourced)
    const int baseLane = lane & 24;

    float V0[DL], V1[DL], V2[DL];
#pragma unroll
    for (int k = 0; k < DL; k++) {
        V0[k] = __ldg(lc + k * DL + l0);
        V1[k] = __ldg(lc + k * DL + l1);
        V2[k] = __ldg(lc + k * DL + l2);
    }

    if (dir == 0)      run_sweep<0>(ew, b, col, l0, full3, baseLane, V0, V1, V2);
    else if (dir == 1) run_sweep<1>(ew, b, col, l0, full3, baseLane, V0, V1, V2);
    else if (dir == 2) run_sweep<2>(ew, b, col, l0, full3, baseLane, V0, V1, V2);
    else               run_sweep<3>(ew, b, col, l0, full3, baseLane, V0, V1, V2);
}

// ---------------------------------------------------------------------------
// out[(b*21+l)*HW + p] = (o0+o1+o2+o3)[(b*HW+p)*21 + l]   (o2 carries -3u)
__global__ void __launch_bounds__(256)
combine(float* __restrict__ out) {
    __shared__ float tile[DL][132];
    const int blk = blockIdx.x;               // 8192
    const int b  = blk >> 11;
    const int p0 = (blk & 2047) << 7;
    const size_t ib = ((size_t)b * HW + p0) * DL;
    for (int j = threadIdx.x; j < (DL * 128) / 4; j += 256) {
        const int f = j << 2;
        float4 a  = *reinterpret_cast<const float4*>(g_o0 + ib + f);
        float4 b4 = *reinterpret_cast<const float4*>(g_o1 + ib + f);
        float4 c  = *reinterpret_cast<const float4*>(g_o2 + ib + f);
        float4 d  = *reinterpret_cast<const float4*>(g_o3 + ib + f);
        tile[(f + 0) % DL][(f + 0) / DL] = a.x + b4.x + c.x + d.x;
        tile[(f + 1) % DL][(f + 1) / DL] = a.y + b4.y + c.y + d.y;
        tile[(f + 2) % DL][(f + 2) / DL] = a.z + b4.z + c.z + d.z;
        tile[(f + 3) % DL][(f + 3) / DL] = a.w + b4.w + c.w + d.w;
    }
    __syncthreads();
    for (int j = threadIdx.x; j < DL * 32; j += 256) {
        const int l = j >> 5, i4 = (j & 31) << 2;
        float4 o = make_float4(tile[l][i4], tile[l][i4 + 1],
                               tile[l][i4 + 2], tile[l][i4 + 3]);
        *reinterpret_cast<float4*>(out + (size_t)(b * DL + l) * HW + p0 + i4) = o;
    }
}

// ---------------------------------------------------------------------------
extern "C" void kernel_launch(void* const* d_in, const int* in_sizes, int n_in,
                              void* d_out, int out_size) {
    const float* unary = (const float*)d_in[0];   // (4,1,21,512,512)
    const float* ew    = (const float*)d_in[1];   // (4,4,512,512)
    const float* lc    = (const float*)d_in[2];   // (21,21)
    float* out = (float*)d_out;                   // (4,1,21,512,512)

    ufuse<<<1024, 256>>>(unary);
    transpose_ew<<<NB * 2 * 256, 256>>>(ew);
    sweep<<<1024, 64>>>(ew, lc);
    combine<<<8192, 256>>>(out);
}